// round 13
// baseline (speedup 1.0000x reference)
#include <cuda_runtime.h>
#include <cuda_fp16.h>
#include <math.h>
#include <stdint.h>

// Problem constants
#define Bq   2
#define Tt   1024
#define Cc   1024
#define Hh   16
#define Ll   6
#define HSs  64
#define Vv   32000
#define FF   4096
#define MR   (Bq*Tt)          // 2048 rows

// ---------------------------------------------------------------------------
// Device scratch (allocation-free)
// ---------------------------------------------------------------------------
__device__ __align__(128) float g_x   [MR * Cc];               // residual
__device__ __align__(128) float g_qkv [MR * 3 * Cc];           // q|k|v fp32
__device__ __align__(128) __half g_a1  [MR * 2 * Cc];          // [Ah|Al] acts, K=1024
__device__ __align__(128) __half g_abig[(size_t)MR * 2 * FF];  // [Ah|Al] acts, K=4096
__device__ __align__(128) __half g_wqkv16[(size_t)Ll * 3 * Cc * Cc]; // [N=3072][K=1024]
__device__ __align__(128) __half g_wo16 [(size_t)Ll * Cc * Cc];
__device__ __align__(128) __half g_w116 [(size_t)Ll * FF * Cc];
__device__ __align__(128) __half g_w216 [(size_t)Ll * Cc * FF];
__device__ __align__(128) __half g_wlm16[(size_t)Vv * Cc];

// ---------------------------------------------------------------------------
// PTX helpers (base compute_103 — no tcgen05)
// ---------------------------------------------------------------------------
__device__ __forceinline__ uint32_t smem_u32(const void* p) {
    uint32_t a;
    asm("{ .reg .u64 t; cvta.to.shared.u64 t, %1; cvt.u32.u64 %0, t; }"
        : "=r"(a) : "l"(p));
    return a;
}

#define CPASYNC16(saddr, gaddr) \
    asm volatile("cp.async.cg.shared.global [%0], [%1], 16;" \
                 :: "r"(saddr), "l"(gaddr) : "memory")
#define CP_COMMIT() asm volatile("cp.async.commit_group;" ::: "memory")
#define CP_WAIT1()  asm volatile("cp.async.wait_group 1;" ::: "memory")

__device__ __forceinline__ void ldsm_x4(uint32_t* r, uint32_t addr) {
    asm volatile("ldmatrix.sync.aligned.m8n8.x4.shared.b16 {%0,%1,%2,%3}, [%4];"
                 : "=r"(r[0]), "=r"(r[1]), "=r"(r[2]), "=r"(r[3]) : "r"(addr));
}

__device__ __forceinline__ void mma_f16(float* c, const uint32_t* a, const uint32_t* b) {
    asm volatile(
        "mma.sync.aligned.m16n8k16.row.col.f32.f16.f16.f32 "
        "{%0,%1,%2,%3}, {%4,%5,%6,%7}, {%8,%9}, {%0,%1,%2,%3};"
        : "+f"(c[0]), "+f"(c[1]), "+f"(c[2]), "+f"(c[3])
        : "r"(a[0]), "r"(a[1]), "r"(a[2]), "r"(a[3]), "r"(b[0]), "r"(b[1]));
}

// ---------------------------------------------------------------------------
// Embedding
// ---------------------------------------------------------------------------
__global__ void __launch_bounds__(256) embed_k(const int* __restrict__ idx,
                                               const float* __restrict__ tok,
                                               const float* __restrict__ pos)
{
    int i = blockIdx.x * 256 + threadIdx.x;
    int bt = i >> 10;
    int c  = i & 1023;
    int token = idx[bt];
    g_x[i] = tok[(size_t)token * Cc + c] + pos[i & (Tt * Cc - 1)];
}

// ---------------------------------------------------------------------------
// QKV weight prep: (L,H,C,HS)x3 -> g_wqkv16 [l][n=w*1024+h*64+d][c] fp16
// ---------------------------------------------------------------------------
__global__ void __launch_bounds__(256) prep_qkv_k(const float* __restrict__ Wq,
                                                  const float* __restrict__ Wk,
                                                  const float* __restrict__ Wv)
{
    const size_t total = (size_t)Ll * 3 * Cc * Cc;
    for (size_t i = (size_t)blockIdx.x * 256 + threadIdx.x; i < total;
         i += (size_t)gridDim.x * 256) {
        int c = (int)(i & 1023);
        size_t r = i >> 10;                  // l*3072 + n
        int n = (int)(r % 3072);
        int l = (int)(r / 3072);
        int w  = n >> 10;
        int cn = n & 1023;
        int hh = cn >> 6;
        int d  = cn & 63;
        const float* src = (w == 0) ? Wq : (w == 1) ? Wk : Wv;
        g_wqkv16[i] = __float2half(src[(((size_t)l * Hh + hh) * Cc + c) * HSs + d]);
    }
}

// ---------------------------------------------------------------------------
// Weight transpose+convert: W fp32 [K,N] -> out fp16 [N,K] (32x32 tiles)
// ---------------------------------------------------------------------------
__device__ __forceinline__ void tconv_tile(const float* __restrict__ W,
                                           __half* __restrict__ out,
                                           int K, int N, int n0, int k0)
{
    __shared__ float s[32][33];
    const int tx = threadIdx.x & 31, ty = threadIdx.x >> 5;
    #pragma unroll
    for (int i = 0; i < 4; i++)
        s[ty + i * 8][tx] = W[(size_t)(k0 + ty + i * 8) * N + n0 + tx];
    __syncthreads();
    #pragma unroll
    for (int i = 0; i < 4; i++) {
        int nl = ty + i * 8;
        out[(size_t)(n0 + nl) * K + k0 + tx] = __float2half(s[tx][nl]);
    }
}

// Wo (6x[1024,1024]) + Wlm ([1024,32000]) : 6144 + 32000 = 38144 blocks
__global__ void __launch_bounds__(256) prep_wA_k(const float* __restrict__ Wo,
                                                 const float* __restrict__ Wlm)
{
    const int bid = blockIdx.x;
    if (bid < 6144) {
        int l = bid >> 10, rem = bid & 1023;
        tconv_tile(Wo + (size_t)l * Cc * Cc, g_wo16 + (size_t)l * Cc * Cc,
                   Cc, Cc, (rem >> 5) << 5, (rem & 31) << 5);
    } else {
        int b2 = bid - 6144;
        tconv_tile(Wlm, g_wlm16, Cc, Vv, (b2 >> 5) << 5, (b2 & 31) << 5);
    }
}

// W1 (6x[1024,4096]) + W2 (6x[4096,1024]) : 24576 + 24576 = 49152 blocks
__global__ void __launch_bounds__(256) prep_wB_k(const float* __restrict__ W1,
                                                 const float* __restrict__ W2)
{
    const int bid = blockIdx.x;
    if (bid < 24576) {
        int l = bid >> 12, rem = bid & 4095;
        tconv_tile(W1 + (size_t)l * Cc * FF, g_w116 + (size_t)l * FF * Cc,
                   Cc, FF, (rem >> 5) << 5, (rem & 31) << 5);
    } else {
        int b2 = bid - 24576;
        int l = b2 >> 12, rem = b2 & 4095;
        tconv_tile(W2 + (size_t)l * FF * Cc, g_w216 + (size_t)l * Cc * FF,
                   FF, Cc, (rem & 31) << 5, (rem >> 5) << 5);
    }
}

// ---------------------------------------------------------------------------
// LayerNorm with fp16 split output: y [M, 2*C] = [Ah | Al]
// ---------------------------------------------------------------------------
__global__ void __launch_bounds__(256) lnsplit_k(const float* __restrict__ x,
                                                 const float* __restrict__ sc,
                                                 const float* __restrict__ bi,
                                                 __half* __restrict__ y)
{
    const int row = blockIdx.x;
    const int tid = threadIdx.x;
    const float4 xv = ((const float4*)(x + (size_t)row * Cc))[tid];
    float s  = xv.x + xv.y + xv.z + xv.w;
    float s2 = xv.x*xv.x + xv.y*xv.y + xv.z*xv.z + xv.w*xv.w;
    __shared__ float r1[8], r2[8];
    #pragma unroll
    for (int o = 16; o; o >>= 1) {
        s  += __shfl_xor_sync(0xffffffffu, s,  o);
        s2 += __shfl_xor_sync(0xffffffffu, s2, o);
    }
    const int lane = tid & 31, w = tid >> 5;
    if (lane == 0) { r1[w] = s; r2[w] = s2; }
    __syncthreads();
    if (tid == 0) {
        float a = 0.f, b = 0.f;
        #pragma unroll
        for (int i = 0; i < 8; i++) { a += r1[i]; b += r2[i]; }
        r1[0] = a; r2[0] = b;
    }
    __syncthreads();
    const float mu   = r1[0] * (1.0f / Cc);
    const float var  = r2[0] * (1.0f / Cc) - mu * mu;
    const float rstd = rsqrtf(var + 1e-5f);
    const float4 sv = ((const float4*)sc)[tid];
    const float4 bv = ((const float4*)bi)[tid];
    float o[4];
    o[0] = (xv.x - mu) * rstd * sv.x + bv.x;
    o[1] = (xv.y - mu) * rstd * sv.y + bv.y;
    o[2] = (xv.z - mu) * rstd * sv.z + bv.z;
    o[3] = (xv.w - mu) * rstd * sv.w + bv.w;
    __half* yr = y + (size_t)row * 2 * Cc;
    #pragma unroll
    for (int j = 0; j < 4; j++) {
        int col = tid * 4 + j;
        __half hi = __float2half(o[j]);
        __half lo = __float2half(o[j] - __half2float(hi));
        yr[col]      = hi;
        yr[Cc + col] = lo;
    }
}

// ---------------------------------------------------------------------------
// HMMA fp16 GEMM: C(M,N) = A'(M,Kt) @ B(N,K)^T  where A'=[Ah|Al] (Kt=2K)
// and B is indexed modulo K (kg & Kmask) so both A halves hit the same B.
// TM x 128 CTA tile, BK=32, 8 warps, 3-stage cp.async pipeline.
// Epilogue: [+bias][+res][relu], out fp32 or fp16-split [M,2N].
// ---------------------------------------------------------------------------
#define ROWB 80          // padded row stride in bytes (32 fp16 = 64B + 16B pad)

template<int TM, bool BIAS, bool RELU, bool RES, bool SPLIT>
__global__ void __launch_bounds__(256, 2)
mm_k(const __half* __restrict__ A,
     const __half* __restrict__ Bp,
     const float* __restrict__ bias,
     const float* __restrict__ res,
     float* __restrict__ Cf,
     __half* __restrict__ Cs,
     int M, int N, int Kt, int Kmask)
{
    constexpr int SA = TM * ROWB;
    constexpr int SB = 128 * ROWB;
    constexpr int SS = SA + SB;
    constexpr int NJ = (TM == 128) ? 8 : 4;

    extern __shared__ uint8_t smem[];
    const uint32_t sb = smem_u32(smem);

    const int tid  = threadIdx.x;
    const int lane = tid & 31;
    const int wid  = tid >> 5;
    const int wm   = (TM == 128) ? (wid & 3) : (wid & 1);
    const int wn   = (TM == 128) ? (wid >> 2) : (wid >> 1);

    const int m0 = blockIdx.x * TM;
    const int n0 = blockIdx.y << 7;

    const int lr   = lane & 7;
    const int g    = lane >> 3;
    const int roff = (g & 1) * 8 + lr;
    const int koff = (g >> 1) * 8;

    const int lrow0 = tid >> 2;
    const int lcol0 = tid & 3;
    const size_t Kb = (size_t)(Kmask + 1);

    float acc[2][NJ][4];
    #pragma unroll
    for (int i = 0; i < 2; i++)
        #pragma unroll
        for (int j = 0; j < NJ; j++)
            #pragma unroll
            for (int q = 0; q < 4; q++) acc[i][j][q] = 0.f;

    const int nk = Kt >> 5;   // BK = 32

    auto loadTile = [&](int kt, int stage) {
        const uint32_t dA = sb + stage * SS;
        const uint32_t dB = dA + SA;
        const int kg = kt * 32;
        const int kb = kg & Kmask;
        CPASYNC16(dA + lrow0 * ROWB + lcol0 * 16,
                  A + (size_t)(m0 + lrow0) * Kt + kg + lcol0 * 8);
        if (TM == 128)
            CPASYNC16(dA + (lrow0 + 64) * ROWB + lcol0 * 16,
                      A + (size_t)(m0 + lrow0 + 64) * Kt + kg + lcol0 * 8);
        CPASYNC16(dB + lrow0 * ROWB + lcol0 * 16,
                  Bp + (size_t)(n0 + lrow0) * Kb + kb + lcol0 * 8);
        CPASYNC16(dB + (lrow0 + 64) * ROWB + lcol0 * 16,
                  Bp + (size_t)(n0 + lrow0 + 64) * Kb + kb + lcol0 * 8);
    };

    loadTile(0, 0); CP_COMMIT();
    loadTile(1, 1); CP_COMMIT();

    int st = 0, stl = 2;
    for (int kt = 0; kt < nk; kt++) {
        CP_WAIT1();
        __syncthreads();
        if (kt + 2 < nk) loadTile(kt + 2, stl);
        CP_COMMIT();

        const uint32_t aT = sb + st * SS;
        const uint32_t bT = aT + SA;

        #pragma unroll
        for (int ks = 0; ks < 2; ks++) {
            uint32_t af[2][4];
            uint32_t bfm[NJ][2];
            #pragma unroll
            for (int i = 0; i < 2; i++)
                ldsm_x4(af[i], aT + (uint32_t)(wm * 32 + i * 16 + roff) * ROWB
                                  + (ks * 16 + koff) * 2);
            #pragma unroll
            for (int j2 = 0; j2 < NJ / 2; j2++) {
                uint32_t r[4];
                ldsm_x4(r, bT + (uint32_t)(wn * (NJ * 8) + j2 * 16 + roff) * ROWB
                             + (ks * 16 + koff) * 2);
                bfm[2 * j2][0]     = r[0];
                bfm[2 * j2 + 1][0] = r[1];
                bfm[2 * j2][1]     = r[2];
                bfm[2 * j2 + 1][1] = r[3];
            }
            #pragma unroll
            for (int i = 0; i < 2; i++)
                #pragma unroll
                for (int j = 0; j < NJ; j++)
                    mma_f16(acc[i][j], af[i], bfm[j]);
        }

        st  = (st  == 2) ? 0 : st  + 1;
        stl = (stl == 2) ? 0 : stl + 1;
    }

    // epilogue
    const int qrow = lane >> 2;
    const int qcol = (lane & 3) * 2;
    #pragma unroll
    for (int i = 0; i < 2; i++) {
        const int rbase = m0 + wm * 32 + i * 16 + qrow;
        #pragma unroll
        for (int j = 0; j < NJ; j++) {
            const int col = n0 + wn * (NJ * 8) + j * 8 + qcol;
            float b0 = 0.f, b1 = 0.f;
            if (BIAS) { b0 = bias[col]; b1 = bias[col + 1]; }
            #pragma unroll
            for (int half = 0; half < 2; half++) {
                const int row = rbase + half * 8;
                float v0 = acc[i][j][half * 2]     + b0;
                float v1 = acc[i][j][half * 2 + 1] + b1;
                if (RES) {
                    const float* rp = res + (size_t)row * N + col;
                    v0 += rp[0]; v1 += rp[1];
                }
                if (RELU) { v0 = fmaxf(v0, 0.f); v1 = fmaxf(v1, 0.f); }
                if (!SPLIT) {
                    float2 o; o.x = v0; o.y = v1;
                    *(float2*)(Cf + (size_t)row * N + col) = o;
                } else {
                    __half h0 = __float2half(v0);
                    __half l0 = __float2half(v0 - __half2float(h0));
                    __half h1 = __float2half(v1);
                    __half l1 = __float2half(v1 - __half2float(h1));
                    __half* cp = Cs + (size_t)row * 2 * N + col;
                    cp[0] = h0;     cp[1] = h1;
                    cp[N] = l0;     cp[N + 1] = l1;
                }
            }
        }
    }
}

// ---------------------------------------------------------------------------
// Flash-tiled attention: block = (qtile of 128, b*h). 256 threads:
// 2 threads per query (even/odd key tiles of 64), merged at the end.
// Output: fp16-split [Ah|Al] rows of width 2048.
// ---------------------------------------------------------------------------
#define ATT_SMEM (24960 * 4)

__global__ void __launch_bounds__(256) fattn_k(const float* __restrict__ qkv,
                                               __half* __restrict__ out)
{
    extern __shared__ float fs[];
    const int qt = blockIdx.x, bh = blockIdx.y;
    const int b = bh >> 4, hh = bh & 15;
    const int tid = threadIdx.x;
    const int qi = tid & 127;
    const int half = tid >> 7;
    const int qrow = qt * 128 + qi;
    const int grow = b * Tt + qrow;

    float* KsH = fs + half * 8192;
    float* VsH = KsH + 4096;
    float* Os  = fs + 16384;
    float* Ms  = Os + 128 * 65;
    float* Ls  = Ms + 128;

    float q[64];
    {
        const float4* qp = (const float4*)(qkv + (size_t)grow * 3072 + hh * 64);
        #pragma unroll
        for (int d4 = 0; d4 < 16; d4++) {
            float4 v = qp[d4];
            q[4*d4] = v.x; q[4*d4+1] = v.y; q[4*d4+2] = v.z; q[4*d4+3] = v.w;
        }
    }

    float o[64];
    #pragma unroll
    for (int d = 0; d < 64; d++) o[d] = 0.f;
    float m = -1e30f, l = 0.f;

    const float* kvb = qkv + (size_t)b * Tt * 3072 + hh * 64;
    const int ntiles = 2 * qt + 2;

    for (int kt = half; kt < ntiles; kt += 2) {
        const int ks0 = kt * 64;
        asm volatile("bar.sync %0, %1;" :: "r"(1 + half), "r"(128) : "memory");
        #pragma unroll
        for (int i = 0; i < 8; i++) {
            int idx = qi + 128 * i;
            int r = idx >> 4, c4 = idx & 15;
            const float4* src = (const float4*)(kvb + (size_t)(ks0 + r) * 3072);
            ((float4*)KsH)[r * 16 + c4] = src[256 + c4];
            ((float4*)VsH)[r * 16 + c4] = src[512 + c4];
        }
        asm volatile("bar.sync %0, %1;" :: "r"(1 + half), "r"(128) : "memory");

        const int lim = qrow - ks0;
        #pragma unroll 1
        for (int c = 0; c < 2; c++) {
            float s[32];
            float tm = -1e30f;
            #pragma unroll
            for (int k = 0; k < 32; k++) {
                const int kk = c * 32 + k;
                const float4* kr = (const float4*)(KsH + kk * 64);
                float a0 = 0.f, a1 = 0.f, a2 = 0.f, a3 = 0.f;
                #pragma unroll
                for (int d4 = 0; d4 < 16; d4++) {
                    float4 kv = kr[d4];
                    a0 += q[4*d4]   * kv.x;
                    a1 += q[4*d4+1] * kv.y;
                    a2 += q[4*d4+2] * kv.z;
                    a3 += q[4*d4+3] * kv.w;
                }
                s[k] = (a0 + a1 + a2 + a3) * 0.125f;
                if (kk <= lim) tm = fmaxf(tm, s[k]);
            }
            const float mn = fmaxf(m, tm);
            const float alpha = __expf(m - mn);
            l *= alpha;
            #pragma unroll
            for (int d = 0; d < 64; d++) o[d] *= alpha;
            #pragma unroll
            for (int k = 0; k < 32; k++) {
                const int kk = c * 32 + k;
                const float p = (kk <= lim) ? __expf(s[k] - mn) : 0.f;
                l += p;
                const float4* vr = (const float4*)(VsH + kk * 64);
                #pragma unroll
                for (int d4 = 0; d4 < 16; d4++) {
                    float4 vv = vr[d4];
                    o[4*d4]   += p * vv.x;
                    o[4*d4+1] += p * vv.y;
                    o[4*d4+2] += p * vv.z;
                    o[4*d4+3] += p * vv.w;
                }
            }
            m = mn;
        }
    }

    __syncthreads();
    if (half == 1) {
        Ms[qi] = m; Ls[qi] = l;
        #pragma unroll
        for (int d = 0; d < 64; d++) Os[qi * 65 + d] = o[d];
    }
    __syncthreads();
    if (half == 0) {
        const float m1 = Ms[qi], l1 = Ls[qi];
        const float mm = fmaxf(m, m1);
        const float a0 = __expf(m - mm), a1 = __expf(m1 - mm);
        const float inv = 1.f / (l * a0 + l1 * a1);
        __half* op = out + (size_t)grow * 2048 + hh * 64;
        #pragma unroll
        for (int d = 0; d < 64; d++) {
            float v = (o[d] * a0 + Os[qi * 65 + d] * a1) * inv;
            __half hi = __float2half(v);
            __half lo = __float2half(v - __half2float(hi));
            op[d]        = hi;
            op[1024 + d] = lo;
        }
    }
}

// ---------------------------------------------------------------------------
// Host launcher
// ---------------------------------------------------------------------------
extern "C" void kernel_launch(void* const* d_in, const int* in_sizes, int n_in,
                              void* d_out, int out_size)
{
    const int*   idx   = (const int*)  d_in[0];
    const float* tok   = (const float*)d_in[1];
    const float* pos   = (const float*)d_in[2];
    const float* Wq    = (const float*)d_in[3];
    const float* Wk    = (const float*)d_in[4];
    const float* Wv    = (const float*)d_in[5];
    const float* Wo    = (const float*)d_in[6];
    const float* bo    = (const float*)d_in[7];
    const float* ln1s  = (const float*)d_in[8];
    const float* ln1b  = (const float*)d_in[9];
    const float* ln2s  = (const float*)d_in[10];
    const float* ln2b  = (const float*)d_in[11];
    const float* W1    = (const float*)d_in[12];
    const float* b1    = (const float*)d_in[13];
    const float* W2    = (const float*)d_in[14];
    const float* b2    = (const float*)d_in[15];
    const float* lnfs  = (const float*)d_in[16];
    const float* lnfb  = (const float*)d_in[17];
    const float* Wlm   = (const float*)d_in[18];
    const float* blm   = (const float*)d_in[19];
    float* out = (float*)d_out;

    float *px, *pqkvf;
    __half *pa1, *pabig, *pwqkv, *pwo, *pw1, *pw2, *pwlm;
    cudaGetSymbolAddress((void**)&px,    g_x);
    cudaGetSymbolAddress((void**)&pqkvf, g_qkv);
    cudaGetSymbolAddress((void**)&pa1,   g_a1);
    cudaGetSymbolAddress((void**)&pabig, g_abig);
    cudaGetSymbolAddress((void**)&pwqkv, g_wqkv16);
    cudaGetSymbolAddress((void**)&pwo,   g_wo16);
    cudaGetSymbolAddress((void**)&pw1,   g_w116);
    cudaGetSymbolAddress((void**)&pw2,   g_w216);
    cudaGetSymbolAddress((void**)&pwlm,  g_wlm16);

    const int SM128 = 3 * (128 * ROWB + 128 * ROWB);  // 61440
    const int SM64  = 3 * (64 * ROWB + 128 * ROWB);   // 46080
    cudaFuncSetAttribute(mm_k<128, false, false, false, false>,
                         cudaFuncAttributeMaxDynamicSharedMemorySize, SM128);
    cudaFuncSetAttribute(mm_k<64, true, false, true, false>,
                         cudaFuncAttributeMaxDynamicSharedMemorySize, SM64);
    cudaFuncSetAttribute(mm_k<128, true, true, false, true>,
                         cudaFuncAttributeMaxDynamicSharedMemorySize, SM128);
    cudaFuncSetAttribute(mm_k<128, true, false, false, false>,
                         cudaFuncAttributeMaxDynamicSharedMemorySize, SM128);
    cudaFuncSetAttribute(fattn_k,
                         cudaFuncAttributeMaxDynamicSharedMemorySize, ATT_SMEM);

    // Launch order puts the layer-0 QKV GEMM at launch index 5 (= ncu capture).
    embed_k<<<(MR * Cc) / 256, 256>>>(idx, tok, pos);                 // 0
    lnsplit_k<<<MR, 256>>>(px, ln1s, ln1b, pa1);                      // 1 (layer 0 ln1)
    prep_qkv_k<<<8192, 256>>>(Wq, Wk, Wv);                            // 2
    prep_wA_k<<<38144, 256>>>(Wo, Wlm);                               // 3
    prep_wB_k<<<49152, 256>>>(W1, W2);                                // 4

    for (int l = 0; l < Ll; ++l) {
        if (l > 0)
            lnsplit_k<<<MR, 256>>>(px, ln1s + (size_t)l * Cc,
                                   ln1b + (size_t)l * Cc, pa1);
        // qkv = a1 @ Wqkv  (2048 x 3072, Kt=2048, K=1024)           // 5 at l=0
        mm_k<128, false, false, false, false><<<dim3(16, 24), 256, SM128>>>(
            pa1, pwqkv + (size_t)l * 3 * Cc * Cc, nullptr, nullptr,
            pqkvf, nullptr, MR, 3 * Cc, 2 * Cc, Cc - 1);
        // flash attention -> split activations
        fattn_k<<<dim3(Tt / 128, Bq * Hh), 256, ATT_SMEM>>>(pqkvf, pa1);
        // x = x + attn @ Wo + bo  (2048 x 1024, Kt=2048, K=1024)
        mm_k<64, true, false, true, false><<<dim3(32, 8), 256, SM64>>>(
            pa1, pwo + (size_t)l * Cc * Cc, bo + (size_t)l * Cc, px,
            px, nullptr, MR, Cc, 2 * Cc, Cc - 1);
        // ln2 -> split
        lnsplit_k<<<MR, 256>>>(px, ln2s + (size_t)l * Cc, ln2b + (size_t)l * Cc, pa1);
        // hidden = relu(a1 @ W1 + b1) -> split  (2048 x 4096, Kt=2048, K=1024)
        mm_k<128, true, true, false, true><<<dim3(16, 32), 256, SM128>>>(
            pa1, pw1 + (size_t)l * FF * Cc, b1 + (size_t)l * FF, nullptr,
            nullptr, pabig, MR, FF, 2 * Cc, Cc - 1);
        // x = x + hidden @ W2 + b2  (2048 x 1024, Kt=8192, K=4096)
        mm_k<64, true, false, true, false><<<dim3(32, 8), 256, SM64>>>(
            pabig, pw2 + (size_t)l * Cc * FF, b2 + (size_t)l * Cc, px,
            px, nullptr, MR, Cc, 2 * FF, FF - 1);
    }

    // final LN + LM head (2048 x 32000, Kt=2048, K=1024)
    lnsplit_k<<<MR, 256>>>(px, lnfs, lnfb, pa1);
    mm_k<128, true, false, false, false><<<dim3(16, 250), 256, SM128>>>(
        pa1, pwlm, blm, nullptr, out, nullptr, MR, Vv, 2 * Cc, Cc - 1);
}

// round 14
// speedup vs baseline: 1.0012x; 1.0012x over previous
#include <cuda_runtime.h>
#include <cuda_fp16.h>
#include <math.h>
#include <stdint.h>

// Problem constants
#define Bq   2
#define Tt   1024
#define Cc   1024
#define Hh   16
#define Ll   6
#define HSs  64
#define Vv   32000
#define FF   4096
#define MR   (Bq*Tt)          // 2048 rows

// ---------------------------------------------------------------------------
// Device scratch (allocation-free)
// ---------------------------------------------------------------------------
__device__ __align__(128) float g_x   [MR * Cc];               // residual
__device__ __align__(128) float g_qkv [MR * 3 * Cc];           // q|k|v fp32
__device__ __align__(128) __half g_a1  [MR * 2 * Cc];          // [Ah|Al] acts, K=1024
__device__ __align__(128) __half g_abig[(size_t)MR * 2 * FF];  // [Ah|Al] acts, K=4096
__device__ __align__(128) __half g_wqkv16[(size_t)Ll * 3 * Cc * Cc]; // [N=3072][K=1024]
__device__ __align__(128) __half g_wo16 [(size_t)Ll * Cc * Cc];
__device__ __align__(128) __half g_w116 [(size_t)Ll * FF * Cc];
__device__ __align__(128) __half g_w216 [(size_t)Ll * Cc * FF];
__device__ __align__(128) __half g_wlm16[(size_t)Vv * Cc];

// ---------------------------------------------------------------------------
// PTX helpers (base compute_103 — no tcgen05)
// ---------------------------------------------------------------------------
__device__ __forceinline__ uint32_t smem_u32(const void* p) {
    uint32_t a;
    asm("{ .reg .u64 t; cvta.to.shared.u64 t, %1; cvt.u32.u64 %0, t; }"
        : "=r"(a) : "l"(p));
    return a;
}

#define CPASYNC16(saddr, gaddr) \
    asm volatile("cp.async.cg.shared.global [%0], [%1], 16;" \
                 :: "r"(saddr), "l"(gaddr) : "memory")
#define CP_COMMIT() asm volatile("cp.async.commit_group;" ::: "memory")
#define CP_WAIT1()  asm volatile("cp.async.wait_group 1;" ::: "memory")

__device__ __forceinline__ void ldsm_x4(uint32_t* r, uint32_t addr) {
    asm volatile("ldmatrix.sync.aligned.m8n8.x4.shared.b16 {%0,%1,%2,%3}, [%4];"
                 : "=r"(r[0]), "=r"(r[1]), "=r"(r[2]), "=r"(r[3]) : "r"(addr));
}

__device__ __forceinline__ void mma_f16(float* c, const uint32_t* a, const uint32_t* b) {
    asm volatile(
        "mma.sync.aligned.m16n8k16.row.col.f32.f16.f16.f32 "
        "{%0,%1,%2,%3}, {%4,%5,%6,%7}, {%8,%9}, {%0,%1,%2,%3};"
        : "+f"(c[0]), "+f"(c[1]), "+f"(c[2]), "+f"(c[3])
        : "r"(a[0]), "r"(a[1]), "r"(a[2]), "r"(a[3]), "r"(b[0]), "r"(b[1]));
}

// ---------------------------------------------------------------------------
// Embedding
// ---------------------------------------------------------------------------
__global__ void __launch_bounds__(256) embed_k(const int* __restrict__ idx,
                                               const float* __restrict__ tok,
                                               const float* __restrict__ pos)
{
    int i = blockIdx.x * 256 + threadIdx.x;
    int bt = i >> 10;
    int c  = i & 1023;
    int token = idx[bt];
    g_x[i] = tok[(size_t)token * Cc + c] + pos[i & (Tt * Cc - 1)];
}

// ---------------------------------------------------------------------------
// QKV weight prep: (L,H,C,HS)x3 -> g_wqkv16 [l][n=w*1024+h*64+d][c] fp16
// ---------------------------------------------------------------------------
__global__ void __launch_bounds__(256) prep_qkv_k(const float* __restrict__ Wq,
                                                  const float* __restrict__ Wk,
                                                  const float* __restrict__ Wv)
{
    const size_t total = (size_t)Ll * 3 * Cc * Cc;
    for (size_t i = (size_t)blockIdx.x * 256 + threadIdx.x; i < total;
         i += (size_t)gridDim.x * 256) {
        int c = (int)(i & 1023);
        size_t r = i >> 10;                  // l*3072 + n
        int n = (int)(r % 3072);
        int l = (int)(r / 3072);
        int w  = n >> 10;
        int cn = n & 1023;
        int hh = cn >> 6;
        int d  = cn & 63;
        const float* src = (w == 0) ? Wq : (w == 1) ? Wk : Wv;
        g_wqkv16[i] = __float2half(src[(((size_t)l * Hh + hh) * Cc + c) * HSs + d]);
    }
}

// ---------------------------------------------------------------------------
// Weight transpose+convert: W fp32 [K,N] -> out fp16 [N,K] (32x32 tiles)
// ---------------------------------------------------------------------------
__device__ __forceinline__ void tconv_tile(const float* __restrict__ W,
                                           __half* __restrict__ out,
                                           int K, int N, int n0, int k0)
{
    __shared__ float s[32][33];
    const int tx = threadIdx.x & 31, ty = threadIdx.x >> 5;
    #pragma unroll
    for (int i = 0; i < 4; i++)
        s[ty + i * 8][tx] = W[(size_t)(k0 + ty + i * 8) * N + n0 + tx];
    __syncthreads();
    #pragma unroll
    for (int i = 0; i < 4; i++) {
        int nl = ty + i * 8;
        out[(size_t)(n0 + nl) * K + k0 + tx] = __float2half(s[tx][nl]);
    }
}

// Wo (6x[1024,1024]) + Wlm ([1024,32000]) : 6144 + 32000 = 38144 blocks
__global__ void __launch_bounds__(256) prep_wA_k(const float* __restrict__ Wo,
                                                 const float* __restrict__ Wlm)
{
    const int bid = blockIdx.x;
    if (bid < 6144) {
        int l = bid >> 10, rem = bid & 1023;
        tconv_tile(Wo + (size_t)l * Cc * Cc, g_wo16 + (size_t)l * Cc * Cc,
                   Cc, Cc, (rem >> 5) << 5, (rem & 31) << 5);
    } else {
        int b2 = bid - 6144;
        tconv_tile(Wlm, g_wlm16, Cc, Vv, (b2 >> 5) << 5, (b2 & 31) << 5);
    }
}

// W1 (6x[1024,4096]) + W2 (6x[4096,1024]) : 24576 + 24576 = 49152 blocks
__global__ void __launch_bounds__(256) prep_wB_k(const float* __restrict__ W1,
                                                 const float* __restrict__ W2)
{
    const int bid = blockIdx.x;
    if (bid < 24576) {
        int l = bid >> 12, rem = bid & 4095;
        tconv_tile(W1 + (size_t)l * Cc * FF, g_w116 + (size_t)l * FF * Cc,
                   Cc, FF, (rem >> 5) << 5, (rem & 31) << 5);
    } else {
        int b2 = bid - 24576;
        int l = b2 >> 12, rem = b2 & 4095;
        tconv_tile(W2 + (size_t)l * FF * Cc, g_w216 + (size_t)l * Cc * FF,
                   FF, Cc, (rem & 31) << 5, (rem >> 5) << 5);
    }
}

// ---------------------------------------------------------------------------
// LayerNorm with fp16 split output: y [M, 2*C] = [Ah | Al]
// ---------------------------------------------------------------------------
__global__ void __launch_bounds__(256) lnsplit_k(const float* __restrict__ x,
                                                 const float* __restrict__ sc,
                                                 const float* __restrict__ bi,
                                                 __half* __restrict__ y)
{
    const int row = blockIdx.x;
    const int tid = threadIdx.x;
    const float4 xv = ((const float4*)(x + (size_t)row * Cc))[tid];
    float s  = xv.x + xv.y + xv.z + xv.w;
    float s2 = xv.x*xv.x + xv.y*xv.y + xv.z*xv.z + xv.w*xv.w;
    __shared__ float r1[8], r2[8];
    #pragma unroll
    for (int o = 16; o; o >>= 1) {
        s  += __shfl_xor_sync(0xffffffffu, s,  o);
        s2 += __shfl_xor_sync(0xffffffffu, s2, o);
    }
    const int lane = tid & 31, w = tid >> 5;
    if (lane == 0) { r1[w] = s; r2[w] = s2; }
    __syncthreads();
    if (tid == 0) {
        float a = 0.f, b = 0.f;
        #pragma unroll
        for (int i = 0; i < 8; i++) { a += r1[i]; b += r2[i]; }
        r1[0] = a; r2[0] = b;
    }
    __syncthreads();
    const float mu   = r1[0] * (1.0f / Cc);
    const float var  = r2[0] * (1.0f / Cc) - mu * mu;
    const float rstd = rsqrtf(var + 1e-5f);
    const float4 sv = ((const float4*)sc)[tid];
    const float4 bv = ((const float4*)bi)[tid];
    float o[4];
    o[0] = (xv.x - mu) * rstd * sv.x + bv.x;
    o[1] = (xv.y - mu) * rstd * sv.y + bv.y;
    o[2] = (xv.z - mu) * rstd * sv.z + bv.z;
    o[3] = (xv.w - mu) * rstd * sv.w + bv.w;
    __half* yr = y + (size_t)row * 2 * Cc;
    #pragma unroll
    for (int j = 0; j < 4; j++) {
        int col = tid * 4 + j;
        __half hi = __float2half(o[j]);
        __half lo = __float2half(o[j] - __half2float(hi));
        yr[col]      = hi;
        yr[Cc + col] = lo;
    }
}

// ---------------------------------------------------------------------------
// HMMA fp16 GEMM: C(M,N) = A'(M,Kt) @ B(N,K)^T  where A'=[Ah|Al] (Kt=2K)
// and B is indexed modulo K (kg & Kmask) so both A halves hit the same B.
// TM x 128 CTA tile, BK=32, 8 warps, 3-stage cp.async pipeline.
// Epilogue: [+bias][+res][relu], out fp32 or fp16-split [M,2N].
// ---------------------------------------------------------------------------
#define ROWB 80          // padded row stride in bytes (32 fp16 = 64B + 16B pad)

template<int TM, bool BIAS, bool RELU, bool RES, bool SPLIT>
__global__ void __launch_bounds__(256, 2)
mm_k(const __half* __restrict__ A,
     const __half* __restrict__ Bp,
     const float* __restrict__ bias,
     const float* __restrict__ res,
     float* __restrict__ Cf,
     __half* __restrict__ Cs,
     int M, int N, int Kt, int Kmask)
{
    constexpr int SA = TM * ROWB;
    constexpr int SB = 128 * ROWB;
    constexpr int SS = SA + SB;
    constexpr int NJ = (TM == 128) ? 8 : 4;

    extern __shared__ uint8_t smem[];
    const uint32_t sb = smem_u32(smem);

    const int tid  = threadIdx.x;
    const int lane = tid & 31;
    const int wid  = tid >> 5;
    const int wm   = (TM == 128) ? (wid & 3) : (wid & 1);
    const int wn   = (TM == 128) ? (wid >> 2) : (wid >> 1);

    const int m0 = blockIdx.x * TM;
    const int n0 = blockIdx.y << 7;

    const int lr   = lane & 7;
    const int g    = lane >> 3;
    const int roff = (g & 1) * 8 + lr;
    const int koff = (g >> 1) * 8;

    const int lrow0 = tid >> 2;
    const int lcol0 = tid & 3;
    const size_t Kb = (size_t)(Kmask + 1);

    float acc[2][NJ][4];
    #pragma unroll
    for (int i = 0; i < 2; i++)
        #pragma unroll
        for (int j = 0; j < NJ; j++)
            #pragma unroll
            for (int q = 0; q < 4; q++) acc[i][j][q] = 0.f;

    const int nk = Kt >> 5;   // BK = 32

    auto loadTile = [&](int kt, int stage) {
        const uint32_t dA = sb + stage * SS;
        const uint32_t dB = dA + SA;
        const int kg = kt * 32;
        const int kb = kg & Kmask;
        CPASYNC16(dA + lrow0 * ROWB + lcol0 * 16,
                  A + (size_t)(m0 + lrow0) * Kt + kg + lcol0 * 8);
        if (TM == 128)
            CPASYNC16(dA + (lrow0 + 64) * ROWB + lcol0 * 16,
                      A + (size_t)(m0 + lrow0 + 64) * Kt + kg + lcol0 * 8);
        CPASYNC16(dB + lrow0 * ROWB + lcol0 * 16,
                  Bp + (size_t)(n0 + lrow0) * Kb + kb + lcol0 * 8);
        CPASYNC16(dB + (lrow0 + 64) * ROWB + lcol0 * 16,
                  Bp + (size_t)(n0 + lrow0 + 64) * Kb + kb + lcol0 * 8);
    };

    loadTile(0, 0); CP_COMMIT();
    loadTile(1, 1); CP_COMMIT();

    int st = 0, stl = 2;
    for (int kt = 0; kt < nk; kt++) {
        CP_WAIT1();
        __syncthreads();
        if (kt + 2 < nk) loadTile(kt + 2, stl);
        CP_COMMIT();

        const uint32_t aT = sb + st * SS;
        const uint32_t bT = aT + SA;

        #pragma unroll
        for (int ks = 0; ks < 2; ks++) {
            uint32_t af[2][4];
            uint32_t bfm[NJ][2];
            #pragma unroll
            for (int i = 0; i < 2; i++)
                ldsm_x4(af[i], aT + (uint32_t)(wm * 32 + i * 16 + roff) * ROWB
                                  + (ks * 16 + koff) * 2);
            #pragma unroll
            for (int j2 = 0; j2 < NJ / 2; j2++) {
                uint32_t r[4];
                ldsm_x4(r, bT + (uint32_t)(wn * (NJ * 8) + j2 * 16 + roff) * ROWB
                             + (ks * 16 + koff) * 2);
                bfm[2 * j2][0]     = r[0];
                bfm[2 * j2 + 1][0] = r[1];
                bfm[2 * j2][1]     = r[2];
                bfm[2 * j2 + 1][1] = r[3];
            }
            #pragma unroll
            for (int i = 0; i < 2; i++)
                #pragma unroll
                for (int j = 0; j < NJ; j++)
                    mma_f16(acc[i][j], af[i], bfm[j]);
        }

        st  = (st  == 2) ? 0 : st  + 1;
        stl = (stl == 2) ? 0 : stl + 1;
    }

    // epilogue
    const int qrow = lane >> 2;
    const int qcol = (lane & 3) * 2;
    #pragma unroll
    for (int i = 0; i < 2; i++) {
        const int rbase = m0 + wm * 32 + i * 16 + qrow;
        #pragma unroll
        for (int j = 0; j < NJ; j++) {
            const int col = n0 + wn * (NJ * 8) + j * 8 + qcol;
            float b0 = 0.f, b1 = 0.f;
            if (BIAS) { b0 = bias[col]; b1 = bias[col + 1]; }
            #pragma unroll
            for (int half = 0; half < 2; half++) {
                const int row = rbase + half * 8;
                float v0 = acc[i][j][half * 2]     + b0;
                float v1 = acc[i][j][half * 2 + 1] + b1;
                if (RES) {
                    const float* rp = res + (size_t)row * N + col;
                    v0 += rp[0]; v1 += rp[1];
                }
                if (RELU) { v0 = fmaxf(v0, 0.f); v1 = fmaxf(v1, 0.f); }
                if (!SPLIT) {
                    float2 o; o.x = v0; o.y = v1;
                    *(float2*)(Cf + (size_t)row * N + col) = o;
                } else {
                    __half h0 = __float2half(v0);
                    __half l0 = __float2half(v0 - __half2float(h0));
                    __half h1 = __float2half(v1);
                    __half l1 = __float2half(v1 - __half2float(h1));
                    __half* cp = Cs + (size_t)row * 2 * N + col;
                    cp[0] = h0;     cp[1] = h1;
                    cp[N] = l0;     cp[N + 1] = l1;
                }
            }
        }
    }
}

// ---------------------------------------------------------------------------
// Flash-tiled attention: block = (qtile of 128, b*h). 256 threads:
// 2 threads per query (even/odd key tiles of 64), merged at the end.
// Output: fp16-split [Ah|Al] rows of width 2048.
// ---------------------------------------------------------------------------
#define ATT_SMEM (24960 * 4)

__global__ void __launch_bounds__(256) fattn_k(const float* __restrict__ qkv,
                                               __half* __restrict__ out)
{
    extern __shared__ float fs[];
    const int qt = blockIdx.x, bh = blockIdx.y;
    const int b = bh >> 4, hh = bh & 15;
    const int tid = threadIdx.x;
    const int qi = tid & 127;
    const int half = tid >> 7;
    const int qrow = qt * 128 + qi;
    const int grow = b * Tt + qrow;

    float* KsH = fs + half * 8192;
    float* VsH = KsH + 4096;
    float* Os  = fs + 16384;
    float* Ms  = Os + 128 * 65;
    float* Ls  = Ms + 128;

    float q[64];
    {
        const float4* qp = (const float4*)(qkv + (size_t)grow * 3072 + hh * 64);
        #pragma unroll
        for (int d4 = 0; d4 < 16; d4++) {
            float4 v = qp[d4];
            q[4*d4] = v.x; q[4*d4+1] = v.y; q[4*d4+2] = v.z; q[4*d4+3] = v.w;
        }
    }

    float o[64];
    #pragma unroll
    for (int d = 0; d < 64; d++) o[d] = 0.f;
    float m = -1e30f, l = 0.f;

    const float* kvb = qkv + (size_t)b * Tt * 3072 + hh * 64;
    const int ntiles = 2 * qt + 2;

    for (int kt = half; kt < ntiles; kt += 2) {
        const int ks0 = kt * 64;
        asm volatile("bar.sync %0, %1;" :: "r"(1 + half), "r"(128) : "memory");
        #pragma unroll
        for (int i = 0; i < 8; i++) {
            int idx = qi + 128 * i;
            int r = idx >> 4, c4 = idx & 15;
            const float4* src = (const float4*)(kvb + (size_t)(ks0 + r) * 3072);
            ((float4*)KsH)[r * 16 + c4] = src[256 + c4];
            ((float4*)VsH)[r * 16 + c4] = src[512 + c4];
        }
        asm volatile("bar.sync %0, %1;" :: "r"(1 + half), "r"(128) : "memory");

        const int lim = qrow - ks0;
        #pragma unroll 1
        for (int c = 0; c < 2; c++) {
            float s[32];
            float tm = -1e30f;
            #pragma unroll
            for (int k = 0; k < 32; k++) {
                const int kk = c * 32 + k;
                const float4* kr = (const float4*)(KsH + kk * 64);
                float a0 = 0.f, a1 = 0.f, a2 = 0.f, a3 = 0.f;
                #pragma unroll
                for (int d4 = 0; d4 < 16; d4++) {
                    float4 kv = kr[d4];
                    a0 += q[4*d4]   * kv.x;
                    a1 += q[4*d4+1] * kv.y;
                    a2 += q[4*d4+2] * kv.z;
                    a3 += q[4*d4+3] * kv.w;
                }
                s[k] = (a0 + a1 + a2 + a3) * 0.125f;
                if (kk <= lim) tm = fmaxf(tm, s[k]);
            }
            const float mn = fmaxf(m, tm);
            const float alpha = __expf(m - mn);
            l *= alpha;
            #pragma unroll
            for (int d = 0; d < 64; d++) o[d] *= alpha;
            #pragma unroll
            for (int k = 0; k < 32; k++) {
                const int kk = c * 32 + k;
                const float p = (kk <= lim) ? __expf(s[k] - mn) : 0.f;
                l += p;
                const float4* vr = (const float4*)(VsH + kk * 64);
                #pragma unroll
                for (int d4 = 0; d4 < 16; d4++) {
                    float4 vv = vr[d4];
                    o[4*d4]   += p * vv.x;
                    o[4*d4+1] += p * vv.y;
                    o[4*d4+2] += p * vv.z;
                    o[4*d4+3] += p * vv.w;
                }
            }
            m = mn;
        }
    }

    __syncthreads();
    if (half == 1) {
        Ms[qi] = m; Ls[qi] = l;
        #pragma unroll
        for (int d = 0; d < 64; d++) Os[qi * 65 + d] = o[d];
    }
    __syncthreads();
    if (half == 0) {
        const float m1 = Ms[qi], l1 = Ls[qi];
        const float mm = fmaxf(m, m1);
        const float a0 = __expf(m - mm), a1 = __expf(m1 - mm);
        const float inv = 1.f / (l * a0 + l1 * a1);
        __half* op = out + (size_t)grow * 2048 + hh * 64;
        #pragma unroll
        for (int d = 0; d < 64; d++) {
            float v = (o[d] * a0 + Os[qi * 65 + d] * a1) * inv;
            __half hi = __float2half(v);
            __half lo = __float2half(v - __half2float(hi));
            op[d]        = hi;
            op[1024 + d] = lo;
        }
    }
}

// ---------------------------------------------------------------------------
// Host launcher
// ---------------------------------------------------------------------------
extern "C" void kernel_launch(void* const* d_in, const int* in_sizes, int n_in,
                              void* d_out, int out_size)
{
    const int*   idx   = (const int*)  d_in[0];
    const float* tok   = (const float*)d_in[1];
    const float* pos   = (const float*)d_in[2];
    const float* Wq    = (const float*)d_in[3];
    const float* Wk    = (const float*)d_in[4];
    const float* Wv    = (const float*)d_in[5];
    const float* Wo    = (const float*)d_in[6];
    const float* bo    = (const float*)d_in[7];
    const float* ln1s  = (const float*)d_in[8];
    const float* ln1b  = (const float*)d_in[9];
    const float* ln2s  = (const float*)d_in[10];
    const float* ln2b  = (const float*)d_in[11];
    const float* W1    = (const float*)d_in[12];
    const float* b1    = (const float*)d_in[13];
    const float* W2    = (const float*)d_in[14];
    const float* b2    = (const float*)d_in[15];
    const float* lnfs  = (const float*)d_in[16];
    const float* lnfb  = (const float*)d_in[17];
    const float* Wlm   = (const float*)d_in[18];
    const float* blm   = (const float*)d_in[19];
    float* out = (float*)d_out;

    float *px, *pqkvf;
    __half *pa1, *pabig, *pwqkv, *pwo, *pw1, *pw2, *pwlm;
    cudaGetSymbolAddress((void**)&px,    g_x);
    cudaGetSymbolAddress((void**)&pqkvf, g_qkv);
    cudaGetSymbolAddress((void**)&pa1,   g_a1);
    cudaGetSymbolAddress((void**)&pabig, g_abig);
    cudaGetSymbolAddress((void**)&pwqkv, g_wqkv16);
    cudaGetSymbolAddress((void**)&pwo,   g_wo16);
    cudaGetSymbolAddress((void**)&pw1,   g_w116);
    cudaGetSymbolAddress((void**)&pw2,   g_w216);
    cudaGetSymbolAddress((void**)&pwlm,  g_wlm16);

    const int SM128 = 3 * (128 * ROWB + 128 * ROWB);  // 61440
    const int SM64  = 3 * (64 * ROWB + 128 * ROWB);   // 46080
    cudaFuncSetAttribute(mm_k<128, false, false, false, false>,
                         cudaFuncAttributeMaxDynamicSharedMemorySize, SM128);
    cudaFuncSetAttribute(mm_k<64, true, false, true, false>,
                         cudaFuncAttributeMaxDynamicSharedMemorySize, SM64);
    cudaFuncSetAttribute(mm_k<128, true, true, false, true>,
                         cudaFuncAttributeMaxDynamicSharedMemorySize, SM128);
    cudaFuncSetAttribute(mm_k<128, true, false, false, false>,
                         cudaFuncAttributeMaxDynamicSharedMemorySize, SM128);
    cudaFuncSetAttribute(fattn_k,
                         cudaFuncAttributeMaxDynamicSharedMemorySize, ATT_SMEM);

    // Launch order puts the layer-0 QKV GEMM at launch index 5 (= ncu capture).
    embed_k<<<(MR * Cc) / 256, 256>>>(idx, tok, pos);                 // 0
    lnsplit_k<<<MR, 256>>>(px, ln1s, ln1b, pa1);                      // 1 (layer 0 ln1)
    prep_qkv_k<<<8192, 256>>>(Wq, Wk, Wv);                            // 2
    prep_wA_k<<<38144, 256>>>(Wo, Wlm);                               // 3
    prep_wB_k<<<49152, 256>>>(W1, W2);                                // 4

    for (int l = 0; l < Ll; ++l) {
        if (l > 0)
            lnsplit_k<<<MR, 256>>>(px, ln1s + (size_t)l * Cc,
                                   ln1b + (size_t)l * Cc, pa1);
        // qkv = a1 @ Wqkv  (2048 x 3072, Kt=2048, K=1024)           // 5 at l=0
        mm_k<128, false, false, false, false><<<dim3(16, 24), 256, SM128>>>(
            pa1, pwqkv + (size_t)l * 3 * Cc * Cc, nullptr, nullptr,
            pqkvf, nullptr, MR, 3 * Cc, 2 * Cc, Cc - 1);
        // flash attention -> split activations
        fattn_k<<<dim3(Tt / 128, Bq * Hh), 256, ATT_SMEM>>>(pqkvf, pa1);
        // x = x + attn @ Wo + bo  (2048 x 1024, Kt=2048, K=1024)
        mm_k<64, true, false, true, false><<<dim3(32, 8), 256, SM64>>>(
            pa1, pwo + (size_t)l * Cc * Cc, bo + (size_t)l * Cc, px,
            px, nullptr, MR, Cc, 2 * Cc, Cc - 1);
        // ln2 -> split
        lnsplit_k<<<MR, 256>>>(px, ln2s + (size_t)l * Cc, ln2b + (size_t)l * Cc, pa1);
        // hidden = relu(a1 @ W1 + b1) -> split  (2048 x 4096, Kt=2048, K=1024)
        mm_k<128, true, true, false, true><<<dim3(16, 32), 256, SM128>>>(
            pa1, pw1 + (size_t)l * FF * Cc, b1 + (size_t)l * FF, nullptr,
            nullptr, pabig, MR, FF, 2 * Cc, Cc - 1);
        // x = x + hidden @ W2 + b2  (2048 x 1024, Kt=8192, K=4096)
        mm_k<64, true, false, true, false><<<dim3(32, 8), 256, SM64>>>(
            pabig, pw2 + (size_t)l * Cc * FF, b2 + (size_t)l * Cc, px,
            px, nullptr, MR, Cc, 2 * FF, FF - 1);
    }

    // final LN + LM head (2048 x 32000, Kt=2048, K=1024)
    lnsplit_k<<<MR, 256>>>(px, lnfs, lnfb, pa1);
    mm_k<128, true, false, false, false><<<dim3(16, 250), 256, SM128>>>(
        pa1, pwlm, blm, nullptr, out, nullptr, MR, Vv, 2 * Cc, Cc - 1);
}